// round 8
// baseline (speedup 1.0000x reference)
#include <cuda_runtime.h>
#include <cuda_fp16.h>
#include <cstdint>
#include <cstring>

// ---------------- problem constants ----------------
#define BATCH   4096
#define IN_F    512
#define OUT_F   512
#define GRID_N  8
#define KSPLINE (IN_F * GRID_N)      // 4096
#define KDIM    (KSPLINE + IN_F)     // 4608

// ---------------- scratch (static device globals: allocation-free) ----------
__device__ __half xn_buf[(size_t)BATCH * IN_F];  // 4 MB tanh(x) fp16
__device__ __half W_buf[(size_t)OUT_F * KDIM];   // ~4.5 MB fp16 weights

// ---------------- helpers ----------------
__device__ __forceinline__ uint32_t smem_u32(const void* p) {
    uint32_t a;
    asm("{ .reg .u64 t; cvta.to.shared.u64 t, %1; cvt.u32.u64 %0, t; }"
        : "=r"(a) : "l"(p));
    return a;
}

#define SMEM_SWZ(off) ((off) ^ (((off) >> 3) & 0x70))

__device__ __forceinline__ void ldsm4(uint32_t& r0, uint32_t& r1,
                                      uint32_t& r2, uint32_t& r3,
                                      uint32_t addr) {
    asm volatile("ldmatrix.sync.aligned.m8n8.x4.shared.b16 {%0,%1,%2,%3}, [%4];"
                 : "=r"(r0), "=r"(r1), "=r"(r2), "=r"(r3) : "r"(addr));
}

__device__ __forceinline__ void mma16816(float* c, const uint32_t* a,
                                         uint32_t b0, uint32_t b1) {
    asm volatile(
        "mma.sync.aligned.m16n8k16.row.col.f32.f16.f16.f32 "
        "{%0,%1,%2,%3}, {%4,%5,%6,%7}, {%8,%9}, {%0,%1,%2,%3};"
        : "+f"(c[0]), "+f"(c[1]), "+f"(c[2]), "+f"(c[3])
        : "r"(a[0]), "r"(a[1]), "r"(a[2]), "r"(a[3]), "r"(b0), "r"(b1));
}

// ---------------- prep: W cast + tanh(x) ----------------
#define W_BLOCKS ((OUT_F * KDIM / 8) / 256)          // 1152
#define X_BLOCKS ((BATCH * IN_F / 8) / 256)          // 1024

__global__ void prep_kernel(const float* __restrict__ x,
                            const float* __restrict__ sw,
                            const float* __restrict__ ba) {
    if (blockIdx.x < W_BLOCKS) {
        int idx8 = blockIdx.x * 256 + threadIdx.x;     // 0 .. 294911
        int o   = idx8 / (KDIM / 8);                   // /576
        int kq  = idx8 - o * (KDIM / 8);
        int k   = kq * 8;
        float v[8];
        if (k < KSPLINE) {
            const float4* src = reinterpret_cast<const float4*>(
                sw + (size_t)o * KSPLINE + k);
            float4 f0 = src[0], f1 = src[1];
            v[0]=f0.x; v[1]=f0.y; v[2]=f0.z; v[3]=f0.w;
            v[4]=f1.x; v[5]=f1.y; v[6]=f1.z; v[7]=f1.w;
        } else {
            const float4* src = reinterpret_cast<const float4*>(
                ba + (size_t)o * IN_F + (k - KSPLINE));
            float4 f0 = src[0], f1 = src[1];
            v[0]=0.1f*f0.x; v[1]=0.1f*f0.y; v[2]=0.1f*f0.z; v[3]=0.1f*f0.w;
            v[4]=0.1f*f1.x; v[5]=0.1f*f1.y; v[6]=0.1f*f1.z; v[7]=0.1f*f1.w;
        }
        __half hv[8];
#pragma unroll
        for (int t = 0; t < 8; t++) hv[t] = __float2half(v[t]);
        *reinterpret_cast<uint4*>(&W_buf[(size_t)o * KDIM + k]) =
            *reinterpret_cast<const uint4*>(hv);
    } else {
        int idx8 = (blockIdx.x - W_BLOCKS) * 256 + threadIdx.x;  // 0..262143
        size_t base = (size_t)idx8 * 8;
        const float4* src = reinterpret_cast<const float4*>(x + base);
        float4 f0 = src[0], f1 = src[1];
        __half hv[8];
        hv[0] = __float2half(tanhf(f0.x)); hv[1] = __float2half(tanhf(f0.y));
        hv[2] = __float2half(tanhf(f0.z)); hv[3] = __float2half(tanhf(f0.w));
        hv[4] = __float2half(tanhf(f1.x)); hv[5] = __float2half(tanhf(f1.y));
        hv[6] = __float2half(tanhf(f1.z)); hv[7] = __float2half(tanhf(f1.w));
        *reinterpret_cast<uint4*>(&xn_buf[base]) =
            *reinterpret_cast<const uint4*>(hv);
    }
}

// ---------------- fused GEMM: D = F(xn) @ W^T, A built in-kernel ----------
#define TM 128
#define TN 128
#define KC 192
#define NITER (KDIM / KC)             // 24
#define GEMM_THREADS 256
#define KBLOCKS 3
#define HALF_TILE_BYTES (128 * 128)   // 128 rows x 64 k fp16 = 16 KB
#define TILE_BYTES  (KBLOCKS * HALF_TILE_BYTES)       // 48 KB per operand
#define STAGE_BYTES (2 * TILE_BYTES)                  // A + B = 96 KB
#define SMEM_DYN_TOTAL (1024 + 2 * STAGE_BYTES)       // ~193 KB

// B-tile loader: 3072 16B chunks, 12 per thread
__device__ __forceinline__ void load_B(uint32_t tiles_base, int it,
                                       int tid, int n0) {
    uint32_t bbase = tiles_base + (uint32_t)(it & 1) * STAGE_BYTES + TILE_BYTES;
    size_t k0 = (size_t)it * KC;
    const __half* Ws = W_buf + (size_t)n0 * KDIM + k0;
#pragma unroll
    for (int c = 0; c < 12; c++) {
        int chunk = tid + c * GEMM_THREADS;     // 0..3071
        int kb   = chunk >> 10;                 // 0..2
        int row  = (chunk >> 3) & 127;
        int q    = chunk & 7;
        const __half* src = Ws + (size_t)row * KDIM + kb * 64 + q * 8;
        uint32_t dst = bbase + (uint32_t)kb * HALF_TILE_BYTES
                     + SMEM_SWZ((uint32_t)(row * 128 + q * 16));
        asm volatile("cp.async.cg.shared.global [%0], [%1], 16;"
                     :: "r"(dst), "l"(src));
    }
    asm volatile("cp.async.commit_group;" ::: "memory");
}

// Build one A cell: 8 fp16 values (one i, 8 grid points) or 8 base columns.
__device__ __forceinline__ void build_cell(int c, int itn, uint32_t Ab,
                                           const __half* __restrict__ xrow,
                                           uint32_t rbase, uint32_t rx,
                                           const float* g) {
    int k_cell = itn * KC + c * 8;
    uint32_t dst = Ab + (uint32_t)(c >> 3) * HALF_TILE_BYTES
                 + rbase + (((uint32_t)((c & 7) * 16)) ^ rx);
    if (k_cell < KSPLINE) {
        float x = __half2float(__ldg(&xrow[k_cell >> 3]));
        uint32_t o[4];
#pragma unroll
        for (int jp = 0; jp < 4; jp++) {
            float v[2];
#pragma unroll
            for (int u = 0; u < 2; u++) {
                float d = fabsf(x - g[jp * 2 + u]);
                bool p = d < 0.5f;
                // inner: 1 - 6d^2 + 6d^3 ; outer: 2(1-d)^3 = 2 - 6d + 6d^2 - 2d^3
                float c3 = p ? 6.0f : -2.0f;
                float c2 = p ? -6.0f : 6.0f;
                float c1 = p ? 0.0f : -6.0f;
                float c0 = p ? 1.0f : 2.0f;
                float t = fmaf(fmaf(fmaf(c3, d, c2), d, c1), d, c0);
                v[u] = fmaxf(t, 0.0f);   // zero for d >= 1
            }
            __half2 h2 = __floats2half2_rn(v[0], v[1]);
            uint32_t bits; memcpy(&bits, &h2, 4);
            o[jp] = bits;
        }
        asm volatile("st.shared.v4.b32 [%0], {%1,%2,%3,%4};"
                     :: "r"(dst), "r"(o[0]), "r"(o[1]), "r"(o[2]), "r"(o[3])
                     : "memory");
    } else {
        uint4 v = __ldg(reinterpret_cast<const uint4*>(&xrow[k_cell - KSPLINE]));
        asm volatile("st.shared.v4.b32 [%0], {%1,%2,%3,%4};"
                     :: "r"(dst), "r"(v.x), "r"(v.y), "r"(v.z), "r"(v.w)
                     : "memory");
    }
}

__global__ void __launch_bounds__(GEMM_THREADS, 1)
kan_gemm_kernel(float* __restrict__ out, const float* __restrict__ gp) {
    extern __shared__ char smem[];
    uint32_t tiles_base = (smem_u32(smem) + 1023u) & ~1023u;

    int tid = threadIdx.x;
    int wid = tid >> 5;
    int lane = tid & 31;
    int m0 = (blockIdx.x >> 2) * TM;     // 32 M-tiles
    int n0 = (blockIdx.x & 3) * TN;      // 4 N-tiles

    // warp sub-tile: 2 (M) x 4 (N) warps, each 64x32
    int wm = (wid >> 2) * 64;
    int wn = (wid & 3) * 32;

    // ldmatrix lane mappings
    int a_row = lane & 15;
    int a_kh  = (lane >> 4) << 3;
    int b_nr  = (lane & 7) + ((lane >> 4) << 3);
    int b_kh  = ((lane >> 3) & 1) << 3;

    // A-builder mapping: thread -> (row r, half h of 24 cells)
    int r = tid & 127;
    int h = tid >> 7;                         // 0..1
    const __half* xrow = xn_buf + (size_t)(m0 + r) * IN_F;
    uint32_t rbase = (uint32_t)(r * 128);
    uint32_t rx    = (uint32_t)((r & 7) * 16);   // swizzle XOR for this row

    float g[8];
#pragma unroll
    for (int j = 0; j < 8; j++) g[j] = __ldg(&gp[j]);

    float acc[4][4][4];
#pragma unroll
    for (int i = 0; i < 4; i++)
#pragma unroll
        for (int j = 0; j < 4; j++)
#pragma unroll
            for (int t = 0; t < 4; t++) acc[i][j][t] = 0.0f;

    // prologue: B(0) via cp.async, A(0) built in-place
    load_B(tiles_base, 0, tid, n0);
#pragma unroll
    for (int cc = 0; cc < 12; cc++)
        build_cell(h * 12 + cc, 0, tiles_base, xrow, rbase, rx, g);

    for (int it = 0; it < NITER; it++) {
        asm volatile("cp.async.wait_group 0;" ::: "memory");
        __syncthreads();

        if (it + 1 < NITER)
            load_B(tiles_base, it + 1, tid, n0);

        uint32_t Ab = tiles_base + (uint32_t)(it & 1) * STAGE_BYTES;
        uint32_t Bb = Ab + TILE_BYTES;
        uint32_t Ab_nxt = tiles_base + (uint32_t)((it + 1) & 1) * STAGE_BYTES;

#pragma unroll
        for (int ks = 0; ks < 12; ks++) {
            uint32_t kboff = (uint32_t)(ks >> 2) * HALF_TILE_BYTES;
            int kk = (ks & 3) * 16;
            uint32_t a[4][4];
#pragma unroll
            for (int mi = 0; mi < 4; mi++) {
                uint32_t addr = Ab + kboff + SMEM_SWZ(
                    (uint32_t)((wm + mi * 16 + a_row) * 128 + (kk + a_kh) * 2));
                ldsm4(a[mi][0], a[mi][1], a[mi][2], a[mi][3], addr);
            }
            uint32_t b[8];
#pragma unroll
            for (int j = 0; j < 2; j++) {
                uint32_t addr = Bb + kboff + SMEM_SWZ(
                    (uint32_t)((wn + j * 16 + b_nr) * 128 + (kk + b_kh) * 2));
                ldsm4(b[j * 4 + 0], b[j * 4 + 1], b[j * 4 + 2], b[j * 4 + 3], addr);
            }
#pragma unroll
            for (int mi = 0; mi < 4; mi++)
#pragma unroll
                for (int nb = 0; nb < 4; nb++)
                    mma16816(acc[mi][nb], a[mi], b[nb * 2], b[nb * 2 + 1]);

            // interleave: build one A cell of iteration it+1 per k-step
            if (it + 1 < NITER)
                build_cell(h * 12 + ks, it + 1, Ab_nxt, xrow, rbase, rx, g);
        }
    }

    // epilogue: register accumulators -> gmem (float2 stores)
    int gq = lane >> 2;
    int q = lane & 3;
#pragma unroll
    for (int mi = 0; mi < 4; mi++) {
#pragma unroll
        for (int nb = 0; nb < 4; nb++) {
            int row = m0 + wm + mi * 16 + gq;
            int col = n0 + wn + nb * 8 + q * 2;
            float2 v0 = make_float2(acc[mi][nb][0], acc[mi][nb][1]);
            float2 v1 = make_float2(acc[mi][nb][2], acc[mi][nb][3]);
            *reinterpret_cast<float2*>(&out[(size_t)row * OUT_F + col]) = v0;
            *reinterpret_cast<float2*>(&out[(size_t)(row + 8) * OUT_F + col]) = v1;
        }
    }
}

// ---------------- launch ----------------
extern "C" void kernel_launch(void* const* d_in, const int* in_sizes, int n_in,
                              void* d_out, int out_size) {
    const float* x  = (const float*)d_in[0];   // (4096, 512)
    const float* sw = (const float*)d_in[1];   // (512, 512, 8)
    const float* ba = (const float*)d_in[2];   // (512, 512)
    const float* gp = (const float*)d_in[3];   // (8,)
    float* out = (float*)d_out;                // (4096, 512)

    prep_kernel<<<W_BLOCKS + X_BLOCKS, 256>>>(x, sw, ba);

    cudaFuncSetAttribute(kan_gemm_kernel,
                         cudaFuncAttributeMaxDynamicSharedMemorySize,
                         SMEM_DYN_TOTAL);
    kan_gemm_kernel<<<(BATCH / TM) * (OUT_F / TN), GEMM_THREADS,
                      SMEM_DYN_TOTAL>>>(out, gp);
}

// round 9
// speedup vs baseline: 1.6521x; 1.6521x over previous
#include <cuda_runtime.h>
#include <cuda_fp16.h>
#include <cstdint>

// ---------------- problem constants ----------------
#define BATCH   4096
#define IN_F    512
#define OUT_F   512
#define GRID_N  8
#define KSPLINE (IN_F * GRID_N)      // 4096
#define KDIM    (KSPLINE + IN_F)     // 4608

// ---------------- scratch (static device globals: allocation-free) ----------
__device__ __half F_buf[(size_t)BATCH * KDIM];   // ~36 MB fp16 features
__device__ __half W_buf[(size_t)OUT_F * KDIM];   // ~4.5 MB fp16 weights

// ---------------- helpers ----------------
__device__ __forceinline__ uint32_t smem_u32(const void* p) {
    uint32_t a;
    asm("{ .reg .u64 t; cvta.to.shared.u64 t, %1; cvt.u32.u64 %0, t; }"
        : "=r"(a) : "l"(p));
    return a;
}

#define SMEM_SWZ(off) ((off) ^ (((off) >> 3) & 0x70))

__device__ __forceinline__ void ldsm4(uint32_t& r0, uint32_t& r1,
                                      uint32_t& r2, uint32_t& r3,
                                      uint32_t addr) {
    asm volatile("ldmatrix.sync.aligned.m8n8.x4.shared.b16 {%0,%1,%2,%3}, [%4];"
                 : "=r"(r0), "=r"(r1), "=r"(r2), "=r"(r3) : "r"(addr));
}

__device__ __forceinline__ void mma16816(float* c, const uint32_t* a,
                                         uint32_t b0, uint32_t b1) {
    asm volatile(
        "mma.sync.aligned.m16n8k16.row.col.f32.f16.f16.f32 "
        "{%0,%1,%2,%3}, {%4,%5,%6,%7}, {%8,%9}, {%0,%1,%2,%3};"
        : "+f"(c[0]), "+f"(c[1]), "+f"(c[2]), "+f"(c[3])
        : "r"(a[0]), "r"(a[1]), "r"(a[2]), "r"(a[3]), "r"(b0), "r"(b1));
}

// fast tanh: overflow-safe, rel err ~1e-6
__device__ __forceinline__ float fast_tanh(float x) {
    float t = __expf(-2.0f * fabsf(x));
    float r = (1.0f - t) / (1.0f + t);
    return copysignf(r, x);
}

// ---------------- prep kernels (high-ILP) ----------------
// W part: 16 elems/thread. 2359296/16/256 = 576 blocks.
#define W_BLOCKS 576
// F part: one thread per (b, 4 i's). 2097152/4/256 = 2048 blocks.
#define F_BLOCKS 2048

__global__ void prep_kernel(const float* __restrict__ x,
                            const float* __restrict__ sw,
                            const float* __restrict__ ba,
                            const float* __restrict__ gp) {
    if (blockIdx.x < W_BLOCKS) {
        int idx16 = blockIdx.x * 256 + threadIdx.x;    // 0 .. 147455
        int o  = idx16 / (KDIM / 16);                  // /288
        int kq = idx16 - o * (KDIM / 16);
        int k  = kq * 16;                              // 16-aligned; region pure
        float v[16];
        if (k < KSPLINE) {
            const float4* src = reinterpret_cast<const float4*>(
                sw + (size_t)o * KSPLINE + k);
#pragma unroll
            for (int j = 0; j < 4; j++) {
                float4 f = src[j];
                v[4*j+0]=f.x; v[4*j+1]=f.y; v[4*j+2]=f.z; v[4*j+3]=f.w;
            }
        } else {
            const float4* src = reinterpret_cast<const float4*>(
                ba + (size_t)o * IN_F + (k - KSPLINE));
#pragma unroll
            for (int j = 0; j < 4; j++) {
                float4 f = src[j];
                v[4*j+0]=0.1f*f.x; v[4*j+1]=0.1f*f.y;
                v[4*j+2]=0.1f*f.z; v[4*j+3]=0.1f*f.w;
            }
        }
        __half hv[16];
#pragma unroll
        for (int t = 0; t < 16; t++) hv[t] = __float2half(v[t]);
        uint4* dst = reinterpret_cast<uint4*>(&W_buf[(size_t)o * KDIM + k]);
        const uint4* s = reinterpret_cast<const uint4*>(hv);
        dst[0] = s[0];
        dst[1] = s[1];
    } else {
        // F part: thread handles (b, i0..i0+3)
        int idx = (blockIdx.x - W_BLOCKS) * 256 + threadIdx.x;  // 0..524287
        int b  = idx >> 7;              // /128  (128 quads per row)
        int i0 = (idx & 127) * 4;

        float4 xv = *reinterpret_cast<const float4*>(
            x + (size_t)b * IN_F + i0);
        float xn[4];
        xn[0] = fast_tanh(xv.x); xn[1] = fast_tanh(xv.y);
        xn[2] = fast_tanh(xv.z); xn[3] = fast_tanh(xv.w);

        float g[8];
#pragma unroll
        for (int j = 0; j < 8; j++) g[j] = __ldg(&gp[j]);

        __half hv[32];
#pragma unroll
        for (int u = 0; u < 4; u++) {
#pragma unroll
            for (int gi = 0; gi < 8; gi++) {
                float d = fabsf(xn[u] - g[gi]);
                bool p = d < 0.5f;
                float c3 = p ?  6.0f : -2.0f;
                float c2 = p ? -6.0f :  6.0f;
                float c1 = p ?  0.0f : -6.0f;
                float c0 = p ?  1.0f :  2.0f;
                float t = fmaf(fmaf(fmaf(c3, d, c2), d, c1), d, c0);
                hv[u * 8 + gi] = __float2half(d < 1.0f ? t : 0.0f);
            }
        }
        // 64B contiguous spline store
        uint4* dst = reinterpret_cast<uint4*>(
            &F_buf[(size_t)b * KDIM + (size_t)i0 * 8]);
        const uint4* s = reinterpret_cast<const uint4*>(hv);
#pragma unroll
        for (int j = 0; j < 4; j++) dst[j] = s[j];
        // 8B base-column store (k = KSPLINE + i0 .. +3)
        __half hb[4];
#pragma unroll
        for (int u = 0; u < 4; u++) hb[u] = __float2half(xn[u]);
        *reinterpret_cast<uint2*>(&F_buf[(size_t)b * KDIM + KSPLINE + i0]) =
            *reinterpret_cast<const uint2*>(hb);
    }
}

// ---------------- mma.sync GEMM: D = F @ W^T (R7, proven) ----------------
// CTA tile 128x128, KC=192 (3 x 64-k half-blocks), 2 stages, 24 iterations.
#define TM 128
#define TN 128
#define KC 192
#define NITER (KDIM / KC)             // 24
#define STAGES 2
#define GEMM_THREADS 256
#define KBLOCKS 3                     // 64-k blocks per K-chunk
#define HALF_TILE_BYTES (128 * 128)   // 128 rows x 64 k fp16 = 16 KB
#define TILE_BYTES  (KBLOCKS * HALF_TILE_BYTES)   // 48 KB per operand
#define STAGE_BYTES (2 * TILE_BYTES)               // A + B = 96 KB
#define SMEM_DYN_TOTAL (1024 + STAGES * STAGE_BYTES)   // ~193 KB

__device__ __forceinline__ void load_stage(uint32_t tiles_base, int it,
                                           int tid, int m0, int n0) {
    uint32_t abase = tiles_base + (uint32_t)(it % STAGES) * STAGE_BYTES;
    size_t k0 = (size_t)it * KC;
    const __half* Fs = F_buf + (size_t)m0 * KDIM + k0;
    const __half* Ws = W_buf + (size_t)n0 * KDIM + k0;
    // 6144 16B-chunks per stage: [A kb0|A kb1|A kb2|B kb0|B kb1|B kb2]
#pragma unroll
    for (int c = 0; c < 24; c++) {
        int chunk = tid + c * GEMM_THREADS;     // 0..6143
        int isB  = (chunk >= 3072);
        int sub  = isB ? (chunk - 3072) : chunk;
        int kb   = sub >> 10;                   // 0..2
        int row  = (sub >> 3) & 127;
        int q    = sub & 7;
        const __half* src = (isB ? Ws : Fs) + (size_t)row * KDIM + kb * 64 + q * 8;
        uint32_t dst = abase + (uint32_t)isB * TILE_BYTES
                     + (uint32_t)kb * HALF_TILE_BYTES
                     + SMEM_SWZ((uint32_t)(row * 128 + q * 16));
        asm volatile("cp.async.cg.shared.global [%0], [%1], 16;"
                     :: "r"(dst), "l"(src));
    }
    asm volatile("cp.async.commit_group;" ::: "memory");
}

__global__ void __launch_bounds__(GEMM_THREADS, 1)
kan_gemm_kernel(float* __restrict__ out) {
    extern __shared__ char smem[];
    uint32_t tiles_base = (smem_u32(smem) + 1023u) & ~1023u;

    int tid = threadIdx.x;
    int wid = tid >> 5;
    int lane = tid & 31;
    int m0 = (blockIdx.x >> 2) * TM;     // 32 M-tiles
    int n0 = (blockIdx.x & 3) * TN;      // 4 N-tiles

    // warp sub-tile: 2 (M) x 4 (N) warps, each 64x32
    int wm = (wid >> 2) * 64;
    int wn = (wid & 3) * 32;

    // ldmatrix lane mappings
    int a_row = lane & 15;
    int a_kh  = (lane >> 4) << 3;
    int b_nr  = (lane & 7) + ((lane >> 4) << 3);
    int b_kh  = ((lane >> 3) & 1) << 3;

    float acc[4][4][4];
#pragma unroll
    for (int i = 0; i < 4; i++)
#pragma unroll
        for (int j = 0; j < 4; j++)
#pragma unroll
            for (int t = 0; t < 4; t++) acc[i][j][t] = 0.0f;

    // preload stage 0
    load_stage(tiles_base, 0, tid, m0, n0);

    for (int it = 0; it < NITER; it++) {
        asm volatile("cp.async.wait_group 0;" ::: "memory");
        __syncthreads();

        if (it + 1 < NITER)
            load_stage(tiles_base, it + 1, tid, m0, n0);

        uint32_t Ab = tiles_base + (uint32_t)(it % STAGES) * STAGE_BYTES;
        uint32_t Bb = Ab + TILE_BYTES;

#pragma unroll
        for (int ks = 0; ks < 12; ks++) {
            uint32_t kboff = (uint32_t)(ks >> 2) * HALF_TILE_BYTES;
            int kk = (ks & 3) * 16;
            uint32_t a[4][4];
#pragma unroll
            for (int mi = 0; mi < 4; mi++) {
                uint32_t addr = Ab + kboff + SMEM_SWZ(
                    (uint32_t)((wm + mi * 16 + a_row) * 128 + (kk + a_kh) * 2));
                ldsm4(a[mi][0], a[mi][1], a[mi][2], a[mi][3], addr);
            }
            uint32_t b[8];
#pragma unroll
            for (int j = 0; j < 2; j++) {
                uint32_t addr = Bb + kboff + SMEM_SWZ(
                    (uint32_t)((wn + j * 16 + b_nr) * 128 + (kk + b_kh) * 2));
                ldsm4(b[j * 4 + 0], b[j * 4 + 1], b[j * 4 + 2], b[j * 4 + 3], addr);
            }
#pragma unroll
            for (int mi = 0; mi < 4; mi++)
#pragma unroll
                for (int nb = 0; nb < 4; nb++)
                    mma16816(acc[mi][nb], a[mi], b[nb * 2], b[nb * 2 + 1]);
        }
    }

    // epilogue: register accumulators -> gmem (float2 stores)
    int g = lane >> 2;
    int q = lane & 3;
#pragma unroll
    for (int mi = 0; mi < 4; mi++) {
#pragma unroll
        for (int nb = 0; nb < 4; nb++) {
            int row = m0 + wm + mi * 16 + g;
            int col = n0 + wn + nb * 8 + q * 2;
            float2 v0 = make_float2(acc[mi][nb][0], acc[mi][nb][1]);
            float2 v1 = make_float2(acc[mi][nb][2], acc[mi][nb][3]);
            *reinterpret_cast<float2*>(&out[(size_t)row * OUT_F + col]) = v0;
            *reinterpret_cast<float2*>(&out[(size_t)(row + 8) * OUT_F + col]) = v1;
        }
    }
}

// ---------------- launch ----------------
extern "C" void kernel_launch(void* const* d_in, const int* in_sizes, int n_in,
                              void* d_out, int out_size) {
    const float* x  = (const float*)d_in[0];   // (4096, 512)
    const float* sw = (const float*)d_in[1];   // (512, 512, 8)
    const float* ba = (const float*)d_in[2];   // (512, 512)
    const float* gp = (const float*)d_in[3];   // (8,)
    float* out = (float*)d_out;                // (4096, 512)

    prep_kernel<<<W_BLOCKS + F_BLOCKS, 256>>>(x, sw, ba, gp);

    cudaFuncSetAttribute(kan_gemm_kernel,
                         cudaFuncAttributeMaxDynamicSharedMemorySize,
                         SMEM_DYN_TOTAL);
    kan_gemm_kernel<<<(BATCH / TM) * (OUT_F / TN), GEMM_THREADS,
                      SMEM_DYN_TOTAL>>>(out);
}